// round 3
// baseline (speedup 1.0000x reference)
#include <cuda_runtime.h>

// LSTM_3444563771996 : I=28, H=64, T=128, B=4096, OUT=10
// Persistent per-CTA LSTM; unified [x;h] K=92 GEMM per step using packed
// fma.rn.f32x2 (FFMA2) to hit the dual-rate fp32 pipe.

#define TI     128
#define II     28
#define HH     64
#define GG     256
#define KK     92
#define BB     4096
#define OUTD   10
#define MB     32
#define NTHR   256
#define ASTR   36

#define SM_W_FLOATS (KK * GG)      // 23552
#define SM_A_FLOATS (KK * ASTR)    // 3312
#define SM_G_FLOATS (MB * GG)      // 8192
#define SMEM_BYTES  ((SM_W_FLOATS + SM_A_FLOATS + SM_G_FLOATS) * 4)  // 140224

typedef unsigned long long u64;

__device__ __forceinline__ u64 packf2(float lo, float hi) {
    u64 d; asm("mov.b64 %0, {%1, %2};" : "=l"(d) : "f"(lo), "f"(hi)); return d;
}
__device__ __forceinline__ void unpackf2(u64 v, float& lo, float& hi) {
    asm("mov.b64 {%0, %1}, %2;" : "=f"(lo), "=f"(hi) : "l"(v));
}
__device__ __forceinline__ u64 fma2(u64 a, u64 b, u64 c) {
    u64 d; asm("fma.rn.f32x2 %0, %1, %2, %3;" : "=l"(d) : "l"(a), "l"(b), "l"(c)); return d;
}

__device__ __forceinline__ float sigm_(float v) {
    return __fdividef(1.0f, 1.0f + __expf(-v));
}
__device__ __forceinline__ float tanh_(float v) {
    float e = __expf(-2.0f * v);
    return __fdividef(2.0f, 1.0f + e) - 1.0f;
}

__global__ __launch_bounds__(NTHR, 1)
void lstm_kernel(const float* __restrict__ x,
                 const float* __restrict__ W_ih, const float* __restrict__ W_hh,
                 const float* __restrict__ b_ih, const float* __restrict__ b_hh,
                 const float* __restrict__ W_out, const float* __restrict__ b_out,
                 float* __restrict__ out)
{
    extern __shared__ float sm[];
    float* Wsm = sm;                         // [KK][GG]   k-major [W_ih|W_hh]^T
    float* Asm = sm + SM_W_FLOATS;           // [KK][ASTR] k<28 -> x_t, k>=28 -> h
    float* Gsm = Asm + SM_A_FLOATS;          // [MB][GG]   gate preacts

    const int tid = threadIdx.x;
    const int b0  = blockIdx.x * MB;

    for (int idx = tid; idx < KK * GG; idx += NTHR) {
        int k = idx >> 8;
        int g = idx & (GG - 1);
        Wsm[idx] = (k < II) ? W_ih[g * II + k] : W_hh[g * HH + (k - II)];
    }
    for (int idx = tid; idx < KK * ASTR; idx += NTHR) Asm[idx] = 0.0f;

    const int gc = tid & 63;
    const int rg = tid >> 6;
    const int g0 = gc * 4;          // 4 gates per thread
    const int r0 = rg * 8;          // 8 rows per thread
    const int u  = tid & 63;

    // combined bias, packed (b,b) for row-pair accumulators
    u64 bp[4];
#pragma unroll
    for (int gi = 0; gi < 4; ++gi) {
        float bv = b_ih[g0 + gi] + b_hh[g0 + gi];
        bp[gi] = packf2(bv, bv);
    }

    float c[8];
#pragma unroll
    for (int r = 0; r < 8; ++r) c[r] = 0.0f;

    __syncthreads();

    for (int t = 0; t < TI; ++t) {
        // ---- stage x_t transposed into Asm[0..27][row] ----
        if (tid < MB * 7) {
            int row = tid / 7;
            int seg = tid - row * 7;
            const float4 xv = *reinterpret_cast<const float4*>(
                x + ((size_t)(b0 + row) * TI + t) * II + seg * 4);
            int ka = seg * 4;
            Asm[(ka + 0) * ASTR + row] = xv.x;
            Asm[(ka + 1) * ASTR + row] = xv.y;
            Asm[(ka + 2) * ASTR + row] = xv.z;
            Asm[(ka + 3) * ASTR + row] = xv.w;
        }
        __syncthreads();   // x_t and h(t-1) ready

        // ---- GEMM: gates[256 x 32] = W[256 x 92] * A[92 x 32] + b ----
        // accp[gi][p] packs rows (r0+2p, r0+2p+1) for gate g0+gi.
        u64 accp[4][4];
#pragma unroll
        for (int gi = 0; gi < 4; ++gi)
#pragma unroll
            for (int p = 0; p < 4; ++p) accp[gi][p] = bp[gi];

#pragma unroll 4
        for (int k = 0; k < KK; ++k) {
            const float4 w = *reinterpret_cast<const float4*>(&Wsm[k * GG + g0]);
            const ulonglong2 q0 = *reinterpret_cast<const ulonglong2*>(&Asm[k * ASTR + r0]);
            const ulonglong2 q1 = *reinterpret_cast<const ulonglong2*>(&Asm[k * ASTR + r0 + 4]);
            const u64 ap[4] = {q0.x, q0.y, q1.x, q1.y};
            const u64 wp[4] = {packf2(w.x, w.x), packf2(w.y, w.y),
                               packf2(w.z, w.z), packf2(w.w, w.w)};
#pragma unroll
            for (int gi = 0; gi < 4; ++gi)
#pragma unroll
                for (int p = 0; p < 4; ++p)
                    accp[gi][p] = fma2(wp[gi], ap[p], accp[gi][p]);
        }

        // ---- unpack + store preacts row-major (STS.128, conflict-free) ----
#pragma unroll
        for (int p = 0; p < 4; ++p) {
            float v0[4], v1[4];
#pragma unroll
            for (int gi = 0; gi < 4; ++gi) unpackf2(accp[gi][p], v0[gi], v1[gi]);
            *reinterpret_cast<float4*>(&Gsm[(r0 + 2 * p) * GG + g0]) =
                make_float4(v0[0], v0[1], v0[2], v0[3]);
            *reinterpret_cast<float4*>(&Gsm[(r0 + 2 * p + 1) * GG + g0]) =
                make_float4(v1[0], v1[1], v1[2], v1[3]);
        }
        __syncthreads();   // preacts visible; GEMM reads of A complete

        // ---- activations + state update; h -> A's k>=28 rows ----
#pragma unroll
        for (int r = 0; r < 8; ++r) {
            const int row = r0 + r;
            const float* gr = &Gsm[row * GG];
            float ig = sigm_(gr[u]);
            float fg = sigm_(gr[u + 64]);
            float gg = tanh_(gr[u + 128]);
            float og = sigm_(gr[u + 192]);
            float cv = fmaf(fg, c[r], ig * gg);
            c[r] = cv;
            Asm[(II + u) * ASTR + row] = og * tanh_(cv);
        }
        // next iteration's top sync orders h writes before the next GEMM.
    }

    // ---- final linear: out = h_T @ W_out^T + b_out ----
    __syncthreads();
    for (int idx = tid; idx < OUTD * HH; idx += NTHR) Gsm[idx] = W_out[idx];
    if (tid < OUTD) Gsm[OUTD * HH + tid] = b_out[tid];
    __syncthreads();

    for (int cell = tid; cell < MB * OUTD; cell += NTHR) {
        int row = cell / OUTD;
        int o   = cell - row * OUTD;
        float s = Gsm[OUTD * HH + o];
#pragma unroll
        for (int j = 0; j < HH; ++j)
            s = fmaf(Asm[(II + j) * ASTR + row], Gsm[o * HH + j], s);
        out[(size_t)(b0 + row) * OUTD + o] = s;
    }
}

extern "C" void kernel_launch(void* const* d_in, const int* in_sizes, int n_in,
                              void* d_out, int out_size)
{
    const float* x     = (const float*)d_in[0];
    const float* W_ih  = (const float*)d_in[1];
    const float* W_hh  = (const float*)d_in[2];
    const float* b_ih  = (const float*)d_in[3];
    const float* b_hh  = (const float*)d_in[4];
    const float* W_out = (const float*)d_in[5];
    const float* b_out = (const float*)d_in[6];
    float* out = (float*)d_out;

    cudaFuncSetAttribute(lstm_kernel,
                         cudaFuncAttributeMaxDynamicSharedMemorySize, SMEM_BYTES);
    lstm_kernel<<<BB / MB, NTHR, SMEM_BYTES>>>(x, W_ih, W_hh, b_ih, b_hh,
                                               W_out, b_out, out);
}

// round 5
// speedup vs baseline: 2.4763x; 2.4763x over previous
#include <cuda_runtime.h>
#include <cuda_bf16.h>
#include <stdint.h>

// LSTM_3444563771996 : I=28, H=64, T=128, B=4096, OUT=10
// Persistent per-CTA LSTM; per-step gates via mma.sync bf16 hi/lo split:
//   D[256,32] = W[256,96] * A[96,32];  D += Whi*Ahi + Whi*Alo + Wlo*Ahi (fp32 acc)

#define TI   128
#define II   28
#define HH   64
#define GG   256
#define KK   92
#define KP   96      // padded K (6 chunks of 16)
#define BB   4096
#define OUTD 10
#define MB   32
#define NTHR 256
#define KST  104     // bf16 row stride (208 B): 16B-aligned, ldmatrix conflict-free
#define GST  33      // Gs float stride (bank-conflict-free activation reads)

// ---- SMEM byte offsets ----
#define SM_WHI 0
#define SM_WLO (SM_WHI + GG * KST * 2)     //  53248
#define SM_AHI (SM_WLO + GG * KST * 2)     // 106496
#define SM_ALO (SM_AHI + MB * KST * 2)     // 113152
#define SM_GS  (SM_ALO + MB * KST * 2)     // 119808
#define SM_HS  (SM_GS  + GG * GST * 4)     // 153600
#define SMEM_BYTES (SM_HS + MB * HH * 4)   // 161792

typedef unsigned long long u64;

#define LDSM4(r, addr)                                                        \
    asm volatile("ldmatrix.sync.aligned.m8n8.x4.shared.b16 {%0,%1,%2,%3}, [%4];" \
                 : "=r"((r)[0]), "=r"((r)[1]), "=r"((r)[2]), "=r"((r)[3])     \
                 : "r"(addr))

#define MMA16816(d, a, b0_, b1_)                                              \
    asm volatile("mma.sync.aligned.m16n8k16.row.col.f32.bf16.bf16.f32 "       \
                 "{%0,%1,%2,%3}, {%4,%5,%6,%7}, {%8,%9}, {%0,%1,%2,%3};"      \
                 : "+f"((d)[0]), "+f"((d)[1]), "+f"((d)[2]), "+f"((d)[3])     \
                 : "r"((a)[0]), "r"((a)[1]), "r"((a)[2]), "r"((a)[3]),        \
                   "r"(b0_), "r"(b1_))

static __device__ __forceinline__ uint32_t smem_u32(const void* p) {
    uint32_t a;
    asm("{ .reg .u64 t; cvta.to.shared.u64 t, %1; cvt.u32.u64 %0, t; }" : "=r"(a) : "l"(p));
    return a;
}
static __device__ __forceinline__ void split_bf16(float v, uint16_t& hi, uint16_t& lo) {
    __nv_bfloat16 h = __float2bfloat16_rn(v);
    __nv_bfloat16 l = __float2bfloat16_rn(v - __bfloat162float(h));
    hi = __bfloat16_as_ushort(h);
    lo = __bfloat16_as_ushort(l);
}
static __device__ __forceinline__ float sigm_(float v) {
    return __fdividef(1.0f, 1.0f + __expf(-v));
}
static __device__ __forceinline__ float tanh_(float v) {
    float e = __expf(-2.0f * v);
    return __fdividef(2.0f, 1.0f + e) - 1.0f;
}

__global__ __launch_bounds__(NTHR, 1)
void lstm_kernel(const float* __restrict__ x,
                 const float* __restrict__ W_ih, const float* __restrict__ W_hh,
                 const float* __restrict__ b_ih, const float* __restrict__ b_hh,
                 const float* __restrict__ W_out, const float* __restrict__ b_out,
                 float* __restrict__ out)
{
    extern __shared__ char smem[];
    const uint32_t sb = smem_u32(smem);
    float* Gs = (float*)(smem + SM_GS);
    float* Hs = (float*)(smem + SM_HS);

    const int tid  = threadIdx.x;
    const int warp = tid >> 5;
    const int lane = tid & 31;
    const int b0   = blockIdx.x * MB;

    // ---- zero W / A staging (K padding + h0 = 0) ----
    for (int i = tid; i < (SM_GS - SM_WHI) / 4; i += NTHR)
        ((uint32_t*)smem)[i] = 0u;
    __syncthreads();

    // ---- stage W hi/lo: [gate][k] bf16, k contiguous ----
    for (int idx = tid; idx < GG * KK; idx += NTHR) {
        int g = idx / KK, k = idx - g * KK;
        float v = (k < II) ? W_ih[g * II + k] : W_hh[g * HH + (k - II)];
        uint16_t hi, lo; split_bf16(v, hi, lo);
        *(uint16_t*)(smem + SM_WHI + (g * KST + k) * 2) = hi;
        *(uint16_t*)(smem + SM_WLO + (g * KST + k) * 2) = lo;
    }

    // ---- per-thread ldmatrix lane offsets ----
    const int l7 = lane & 7, lg = lane >> 3;
    // W (A-operand) tiles: {rows0-7@k0, rows8-15@k0, rows0-7@k8, rows8-15@k8}
    const int wrow = l7 + ((lg & 1) << 3);
    const int wkh  = lg >> 1;
    // Activation (B-operand) tiles: {n0-7@k0, n0-7@k8, n8-15@k0, n8-15@k8}
    const int arow = l7 + ((lg >> 1) << 3);
    const int akh  = lg & 1;

    const uint32_t woffH = sb + SM_WHI + (((warp * 32 + wrow) * KST) + wkh * 8) * 2;
    const uint32_t woffL = sb + SM_WLO + (((warp * 32 + wrow) * KST) + wkh * 8) * 2;
    const uint32_t aoffH = sb + SM_AHI + ((arow * KST) + akh * 8) * 2;
    const uint32_t aoffL = sb + SM_ALO + ((arow * KST) + akh * 8) * 2;

    // ---- activation-phase constants ----
    const int u  = tid & 63;
    const int rg = tid >> 6;
    const int r0 = rg * 8;
    const float bi = b_ih[u]       + b_hh[u];
    const float bf = b_ih[u + 64]  + b_hh[u + 64];
    const float bg = b_ih[u + 128] + b_hh[u + 128];
    const float bo = b_ih[u + 192] + b_hh[u + 192];

    float c[8];
#pragma unroll
    for (int r = 0; r < 8; ++r) c[r] = 0.0f;

    const int grow = lane >> 2;        // accum row within m8
    const int bcol = (lane & 3) * 2;   // accum col pair

    __syncthreads();

    for (int t = 0; t < TI; ++t) {
        // ---- stage x_t: bf16 hi/lo at A[row][0..27] ----
        if (tid < MB * 7) {
            int row = tid / 7, seg = tid - row * 7;
            const float4 xv = *reinterpret_cast<const float4*>(
                x + ((size_t)(b0 + row) * TI + t) * II + seg * 4);
            uint16_t h0,l0,h1,l1,h2,l2,h3,l3;
            split_bf16(xv.x, h0, l0); split_bf16(xv.y, h1, l1);
            split_bf16(xv.z, h2, l2); split_bf16(xv.w, h3, l3);
            u64 ph = (u64)h0 | ((u64)h1 << 16) | ((u64)h2 << 32) | ((u64)h3 << 48);
            u64 pl = (u64)l0 | ((u64)l1 << 16) | ((u64)l2 << 32) | ((u64)l3 << 48);
            *(u64*)(smem + SM_AHI + (row * KST + seg * 4) * 2) = ph;
            *(u64*)(smem + SM_ALO + (row * KST + seg * 4) * 2) = pl;
        }
        __syncthreads();   // x_t + h(t-1) visible

        // ---- GEMM: 144 HMMA / warp ----
        float acc[2][4][4];
#pragma unroll
        for (int mt = 0; mt < 2; ++mt)
#pragma unroll
            for (int nt = 0; nt < 4; ++nt)
#pragma unroll
                for (int q = 0; q < 4; ++q) acc[mt][nt][q] = 0.0f;

#pragma unroll
        for (int kc = 0; kc < 6; ++kc) {
            const uint32_t ko = kc * 32;   // bytes
            uint32_t whi[2][4], wlo[2][4], bhi[2][4], blo[2][4];
            LDSM4(whi[0], woffH + ko);
            LDSM4(whi[1], woffH + 16 * KST * 2 + ko);
            LDSM4(wlo[0], woffL + ko);
            LDSM4(wlo[1], woffL + 16 * KST * 2 + ko);
            LDSM4(bhi[0], aoffH + ko);
            LDSM4(bhi[1], aoffH + 16 * KST * 2 + ko);
            LDSM4(blo[0], aoffL + ko);
            LDSM4(blo[1], aoffL + 16 * KST * 2 + ko);
#pragma unroll
            for (int mt = 0; mt < 2; ++mt)
#pragma unroll
                for (int nh = 0; nh < 2; ++nh)
#pragma unroll
                    for (int j = 0; j < 2; ++j) {
                        float* d = acc[mt][nh * 2 + j];
                        MMA16816(d, whi[mt], bhi[nh][2*j], bhi[nh][2*j+1]);
                        MMA16816(d, whi[mt], blo[nh][2*j], blo[nh][2*j+1]);
                        MMA16816(d, wlo[mt], bhi[nh][2*j], bhi[nh][2*j+1]);
                    }
        }

        // ---- store gates to Gs[gate][GST] ----
#pragma unroll
        for (int mt = 0; mt < 2; ++mt)
#pragma unroll
            for (int nt = 0; nt < 4; ++nt) {
                const int g1 = warp * 32 + mt * 16 + grow;
                const int bb = nt * 8 + bcol;
                Gs[g1 * GST + bb]           = acc[mt][nt][0];
                Gs[g1 * GST + bb + 1]       = acc[mt][nt][1];
                Gs[(g1 + 8) * GST + bb]     = acc[mt][nt][2];
                Gs[(g1 + 8) * GST + bb + 1] = acc[mt][nt][3];
            }
        __syncthreads();   // gates visible; A reads complete

        // ---- activations + state update; h -> A[row][28+u] hi/lo ----
#pragma unroll
        for (int r = 0; r < 8; ++r) {
            const int row = r0 + r;
            float ig = sigm_(Gs[u * GST + row]          + bi);
            float fg = sigm_(Gs[(u + 64) * GST + row]   + bf);
            float gg = tanh_(Gs[(u + 128) * GST + row]  + bg);
            float og = sigm_(Gs[(u + 192) * GST + row]  + bo);
            float cv = fmaf(fg, c[r], ig * gg);
            c[r] = cv;
            float hv = og * tanh_(cv);
            uint16_t hh, hl; split_bf16(hv, hh, hl);
            *(uint16_t*)(smem + SM_AHI + (row * KST + II + u) * 2) = hh;
            *(uint16_t*)(smem + SM_ALO + (row * KST + II + u) * 2) = hl;
            if (t == TI - 1) Hs[row * HH + u] = hv;
        }
        // next iteration's top sync orders h writes before ldmatrix reads.
    }

    // ---- final linear: out = h_T @ W_out^T + b_out ----
    __syncthreads();
    for (int idx = tid; idx < OUTD * HH; idx += NTHR) Gs[idx] = W_out[idx];
    if (tid < OUTD) Gs[OUTD * HH + tid] = b_out[tid];
    __syncthreads();

    for (int cell = tid; cell < MB * OUTD; cell += NTHR) {
        int row = cell / OUTD;
        int o   = cell - row * OUTD;
        float s = Gs[OUTD * HH + o];
#pragma unroll
        for (int j = 0; j < HH; ++j)
            s = fmaf(Hs[row * HH + j], Gs[o * HH + j], s);
        out[(size_t)(b0 + row) * OUTD + o] = s;
    }
}

extern "C" void kernel_launch(void* const* d_in, const int* in_sizes, int n_in,
                              void* d_out, int out_size)
{
    const float* x     = (const float*)d_in[0];
    const float* W_ih  = (const float*)d_in[1];
    const float* W_hh  = (const float*)d_in[2];
    const float* b_ih  = (const float*)d_in[3];
    const float* b_hh  = (const float*)d_in[4];
    const float* W_out = (const float*)d_in[5];
    const float* b_out = (const float*)d_in[6];
    float* outp = (float*)d_out;

    cudaFuncSetAttribute(lstm_kernel,
                         cudaFuncAttributeMaxDynamicSharedMemorySize, SMEM_BYTES);
    lstm_kernel<<<BB / MB, NTHR, SMEM_BYTES>>>(x, W_ih, W_hh, b_ih, b_hh,
                                               W_out, b_out, outp);
}

// round 6
// speedup vs baseline: 3.1812x; 1.2846x over previous
#include <cuda_runtime.h>
#include <cuda_bf16.h>
#include <stdint.h>

// LSTM_3444563771996 : I=28, H=64, T=128, B=4096, OUT=10
// Persistent per-CTA LSTM, bf16 hi/lo split mma.sync.
// 512 threads = 2 independent groups of 256, each owning 16 batch rows with
// private named barriers -> GEMM of one group overlaps activations of the other.

#define TI   128
#define II   28
#define HH   64
#define GG   256
#define KK   92
#define BB   4096
#define OUTD 10
#define MB   32      // batch rows per CTA (16 per group)
#define NTHR 512
#define KST  104     // bf16 row stride (208 B)
#define GST  33      // Gs float stride

#define SM_WHI 0
#define SM_WLO (SM_WHI + GG * KST * 2)     //  53248
#define SM_AHI (SM_WLO + GG * KST * 2)     // 106496
#define SM_ALO (SM_AHI + MB * KST * 2)     // 113152
#define SM_GS  (SM_ALO + MB * KST * 2)     // 119808
#define SM_HS  (SM_GS  + GG * GST * 4)     // 153600
#define SMEM_BYTES (SM_HS + MB * HH * 4)   // 161792

typedef unsigned long long u64;

#define LDSM4(r, addr)                                                        \
    asm volatile("ldmatrix.sync.aligned.m8n8.x4.shared.b16 {%0,%1,%2,%3}, [%4];" \
                 : "=r"((r)[0]), "=r"((r)[1]), "=r"((r)[2]), "=r"((r)[3])     \
                 : "r"(addr))

#define MMA16816(d, a, b0_, b1_)                                              \
    asm volatile("mma.sync.aligned.m16n8k16.row.col.f32.bf16.bf16.f32 "       \
                 "{%0,%1,%2,%3}, {%4,%5,%6,%7}, {%8,%9}, {%0,%1,%2,%3};"      \
                 : "+f"((d)[0]), "+f"((d)[1]), "+f"((d)[2]), "+f"((d)[3])     \
                 : "r"((a)[0]), "r"((a)[1]), "r"((a)[2]), "r"((a)[3]),        \
                   "r"(b0_), "r"(b1_))

#define GBAR(id)                                                              \
    asm volatile("bar.sync %0, %1;" :: "r"(id), "r"(256) : "memory")

static __device__ __forceinline__ uint32_t smem_u32(const void* p) {
    uint32_t a;
    asm("{ .reg .u64 t; cvta.to.shared.u64 t, %1; cvt.u32.u64 %0, t; }" : "=r"(a) : "l"(p));
    return a;
}
static __device__ __forceinline__ void split_bf16(float v, uint16_t& hi, uint16_t& lo) {
    __nv_bfloat16 h = __float2bfloat16_rn(v);
    __nv_bfloat16 l = __float2bfloat16_rn(v - __bfloat162float(h));
    hi = __bfloat16_as_ushort(h);
    lo = __bfloat16_as_ushort(l);
}
static __device__ __forceinline__ float sigm_(float v) {
    return __fdividef(1.0f, 1.0f + __expf(-v));
}
static __device__ __forceinline__ float tanh_(float v) {
    float e = __expf(-2.0f * v);
    return __fdividef(2.0f, 1.0f + e) - 1.0f;
}

__global__ __launch_bounds__(NTHR, 1)
void lstm_kernel(const float* __restrict__ x,
                 const float* __restrict__ W_ih, const float* __restrict__ W_hh,
                 const float* __restrict__ b_ih, const float* __restrict__ b_hh,
                 const float* __restrict__ W_out, const float* __restrict__ b_out,
                 float* __restrict__ out)
{
    extern __shared__ char smem[];
    const uint32_t sb = smem_u32(smem);
    float* Gs = (float*)(smem + SM_GS);
    float* Hs = (float*)(smem + SM_HS);

    const int tid   = threadIdx.x;
    const int lane  = tid & 31;
    const int group = tid >> 8;          // 0 or 1: owns batch rows [group*16, +16)
    const int gtid  = tid & 255;
    const int gwarp = (tid >> 5) & 7;    // warp within group -> 32-gate slice
    const int b0    = blockIdx.x * MB;
    const int barid = 1 + group;

    // ---- zero W / A staging (K padding + h0 = 0) ----
    for (int i = tid; i < (SM_GS - SM_WHI) / 4; i += NTHR)
        ((uint32_t*)smem)[i] = 0u;
    __syncthreads();

    // ---- stage W hi/lo: [gate][k] bf16 ----
    for (int idx = tid; idx < GG * KK; idx += NTHR) {
        int g = idx / KK, k = idx - g * KK;
        float v = (k < II) ? W_ih[g * II + k] : W_hh[g * HH + (k - II)];
        uint16_t hi, lo; split_bf16(v, hi, lo);
        *(uint16_t*)(smem + SM_WHI + (g * KST + k) * 2) = hi;
        *(uint16_t*)(smem + SM_WLO + (g * KST + k) * 2) = lo;
    }
    __syncthreads();

    // ---- ldmatrix lane offsets ----
    const int l7 = lane & 7, lg = lane >> 3;
    const int wrow = l7 + ((lg & 1) << 3);           // W tiles {r0-7@k0, r8-15@k0, r0-7@k8, r8-15@k8}
    const int wkh  = lg >> 1;
    const int arow = group * 16 + l7 + ((lg >> 1) << 3);  // B tiles {n0-7@k0, n0-7@k8, n8-15@k0, n8-15@k8}
    const int akh  = lg & 1;

    const uint32_t woffH = sb + SM_WHI + (((gwarp * 32 + wrow) * KST) + wkh * 8) * 2;
    const uint32_t woffL = sb + SM_WLO + (((gwarp * 32 + wrow) * KST) + wkh * 8) * 2;
    const uint32_t aoffH = sb + SM_AHI + ((arow * KST) + akh * 8) * 2;
    const uint32_t aoffL = sb + SM_ALO + ((arow * KST) + akh * 8) * 2;

    // ---- preload W-hi fragments into registers (persist across t) ----
    uint32_t whiR[6][2][4];
#pragma unroll
    for (int kc = 0; kc < 6; ++kc)
#pragma unroll
        for (int mt = 0; mt < 2; ++mt)
            LDSM4(whiR[kc][mt], woffH + mt * 16 * KST * 2 + kc * 32);

    // ---- accumulator-row biases (folded into acc init) ----
    const int grow = lane >> 2;          // accum row within m8
    const int bcol = (lane & 3) * 2;     // accum col pair
    float biasA[2], biasB[2];
#pragma unroll
    for (int mt = 0; mt < 2; ++mt) {
        int g1 = gwarp * 32 + mt * 16 + grow;
        biasA[mt] = b_ih[g1]     + b_hh[g1];
        biasB[mt] = b_ih[g1 + 8] + b_hh[g1 + 8];
    }

    // ---- activation-phase constants (per group: 256 threads, 4 rows each) ----
    const int u  = gtid & 63;
    const int rg = gtid >> 6;            // 0..3
    const int r0 = group * 16 + rg * 4;  // global batch row base
    float c[4];
#pragma unroll
    for (int r = 0; r < 4; ++r) c[r] = 0.0f;

    __syncthreads();

    for (int t = 0; t < TI; ++t) {
        // ---- stage x_t for this group's 16 rows ----
        if (gtid < 16 * 7) {
            int row = group * 16 + gtid / 7, seg = gtid % 7;
            const float4 xv = *reinterpret_cast<const float4*>(
                x + ((size_t)(b0 + row) * TI + t) * II + seg * 4);
            uint16_t h0,l0,h1,l1,h2,l2,h3,l3;
            split_bf16(xv.x, h0, l0); split_bf16(xv.y, h1, l1);
            split_bf16(xv.z, h2, l2); split_bf16(xv.w, h3, l3);
            u64 ph = (u64)h0 | ((u64)h1 << 16) | ((u64)h2 << 32) | ((u64)h3 << 48);
            u64 pl = (u64)l0 | ((u64)l1 << 16) | ((u64)l2 << 32) | ((u64)l3 << 48);
            *(u64*)(smem + SM_AHI + (row * KST + seg * 4) * 2) = ph;
            *(u64*)(smem + SM_ALO + (row * KST + seg * 4) * 2) = pl;
        }
        GBAR(barid);   // group's x_t + h(t-1) visible

        // ---- GEMM: 72 HMMA/warp, D[256 gates, 16 batch] ----
        float acc[2][2][4];
#pragma unroll
        for (int mt = 0; mt < 2; ++mt)
#pragma unroll
            for (int j = 0; j < 2; ++j) {
                acc[mt][j][0] = biasA[mt]; acc[mt][j][1] = biasA[mt];
                acc[mt][j][2] = biasB[mt]; acc[mt][j][3] = biasB[mt];
            }

#pragma unroll
        for (int kc = 0; kc < 6; ++kc) {
            const uint32_t ko = kc * 32;
            uint32_t wlo0[4], wlo1[4], bhi[4], blo[4];
            LDSM4(wlo0, woffL + ko);
            LDSM4(wlo1, woffL + 16 * KST * 2 + ko);
            LDSM4(bhi, aoffH + ko);
            LDSM4(blo, aoffL + ko);
#pragma unroll
            for (int mt = 0; mt < 2; ++mt) {
                uint32_t* wl = mt ? wlo1 : wlo0;
#pragma unroll
                for (int j = 0; j < 2; ++j) {
                    float* d = acc[mt][j];
                    MMA16816(d, whiR[kc][mt], bhi[2*j], bhi[2*j+1]);
                    MMA16816(d, whiR[kc][mt], blo[2*j], blo[2*j+1]);
                    MMA16816(d, wl,           bhi[2*j], bhi[2*j+1]);
                }
            }
        }

        // ---- store gates to Gs[gate][group cols] ----
#pragma unroll
        for (int mt = 0; mt < 2; ++mt)
#pragma unroll
            for (int j = 0; j < 2; ++j) {
                const int g1 = gwarp * 32 + mt * 16 + grow;
                const int bb = group * 16 + j * 8 + bcol;
                Gs[g1 * GST + bb]           = acc[mt][j][0];
                Gs[g1 * GST + bb + 1]       = acc[mt][j][1];
                Gs[(g1 + 8) * GST + bb]     = acc[mt][j][2];
                Gs[(g1 + 8) * GST + bb + 1] = acc[mt][j][3];
            }
        GBAR(barid);   // gates visible; group's A reads complete

        // ---- activations + state update; h -> A[row][28+u] hi/lo ----
#pragma unroll
        for (int r = 0; r < 4; ++r) {
            const int row = r0 + r;
            float ig = sigm_(Gs[u * GST + row]);
            float fg = sigm_(Gs[(u + 64) * GST + row]);
            float gg = tanh_(Gs[(u + 128) * GST + row]);
            float og = sigm_(Gs[(u + 192) * GST + row]);
            float cv = fmaf(fg, c[r], ig * gg);
            c[r] = cv;
            float hv = og * tanh_(cv);
            uint16_t hh, hl; split_bf16(hv, hh, hl);
            *(uint16_t*)(smem + SM_AHI + (row * KST + II + u) * 2) = hh;
            *(uint16_t*)(smem + SM_ALO + (row * KST + II + u) * 2) = hl;
            if (t == TI - 1) Hs[row * HH + u] = hv;
        }
        // next iteration's group barrier orders h writes before ldmatrix reads.
    }

    // ---- final linear: out = h_T @ W_out^T + b_out ----
    __syncthreads();
    for (int idx = tid; idx < OUTD * HH; idx += NTHR) Gs[idx] = W_out[idx];
    if (tid < OUTD) Gs[OUTD * HH + tid] = b_out[tid];
    __syncthreads();

    for (int cell = tid; cell < MB * OUTD; cell += NTHR) {
        int row = cell / OUTD;
        int o   = cell - row * OUTD;
        float s = Gs[OUTD * HH + o];
#pragma unroll
        for (int j = 0; j < HH; ++j)
            s = fmaf(Hs[row * HH + j], Gs[o * HH + j], s);
        out[(size_t)(b0 + row) * OUTD + o] = s;
    }
}

extern "C" void kernel_launch(void* const* d_in, const int* in_sizes, int n_in,
                              void* d_out, int out_size)
{
    const float* x     = (const float*)d_in[0];
    const float* W_ih  = (const float*)d_in[1];
    const float* W_hh  = (const float*)d_in[2];
    const float* b_ih  = (const float*)d_in[3];
    const float* b_hh  = (const float*)d_in[4];
    const float* W_out = (const float*)d_in[5];
    const float* b_out = (const float*)d_in[6];
    float* outp = (float*)d_out;

    cudaFuncSetAttribute(lstm_kernel,
                         cudaFuncAttributeMaxDynamicSharedMemorySize, SMEM_BYTES);
    lstm_kernel<<<BB / MB, NTHR, SMEM_BYTES>>>(x, W_ih, W_hh, b_ih, b_hh,
                                               W_out, b_out, outp);
}